// round 4
// baseline (speedup 1.0000x reference)
#include <cuda_runtime.h>

// LabelWiseAttn fused flash-style kernel — fp32 with packed f32x2 FMAs.
//   att[b,c,l] = U[c,:] . x[b,l,:]
//   alpha      = softmax_l(att)       (|att| <~ 1.1 -> no max-subtraction needed)
//   m[b,c,d]   = sum_l alpha[b,c,l] * x[b,l,d]
//
// Per CTA: one (batch, 128-class tile); stream L in 64-row chunks; att never
// hits global memory. Inner loops use fma.rn.f32x2 (FFMA2, PTX-only — ptxas
// never emits it) for 2 fp32 MACs per issue slot.
// R3 refinements: register-path transpose (no smem read-back, 2-way STS
// conflicts instead of 4-way, one fewer barrier per chunk) and LDG prefetch
// of the next x chunk overlapped with GEMM2.

#define BATCH    8
#define SEQ      2500
#define DIM      128
#define NCLS     8921
#define CT       128      // class tile per CTA
#define LT       64       // sequence chunk
#define NTHREADS 256

#define US_LD 132         // Us row stride (floats); 528B rows, 16B-aligned
#define XT_LD 68          // xt row stride (floats); 272B rows, 16B-aligned
#define PS_LD 128
#define XS_LD 128

#define US_SIZE (DIM * US_LD)     // 16896 floats
#define XS_SIZE (LT  * XS_LD)     //  8192
#define XT_SIZE (DIM * XT_LD)     //  8704
#define PS_SIZE (LT  * PS_LD)     //  8192
#define SMEM_FLOATS (US_SIZE + XS_SIZE + XT_SIZE + PS_SIZE + CT)   // -> 168448 B

typedef unsigned long long u64;

// (v, v) packed f32x2
__device__ __forceinline__ u64 splat2(float v) {
    unsigned int u = __float_as_uint(v);
    u64 r;
    asm("mov.b64 %0, {%1, %2};" : "=l"(r) : "r"(u), "r"(u));
    return r;
}

// d = a*b + c, elementwise on 2 packed fp32 lanes (bit-exact IEEE fp32)
__device__ __forceinline__ u64 fma2(u64 a, u64 b, u64 c) {
    u64 d;
    asm("fma.rn.f32x2 %0, %1, %2, %3;" : "=l"(d) : "l"(a), "l"(b), "l"(c));
    return d;
}

__device__ __forceinline__ void unpack2(u64 v, float& lo, float& hi) {
    unsigned int a, b;
    asm("mov.b64 {%0, %1}, %2;" : "=r"(a), "=r"(b) : "l"(v));
    lo = __uint_as_float(a);
    hi = __uint_as_float(b);
}

__global__ __launch_bounds__(NTHREADS, 1)
void lwa_kernel(const float* __restrict__ x,
                const float* __restrict__ U,
                float* __restrict__ out)
{
    extern __shared__ float sm[];
    float* Us    = sm;                      // [DIM][US_LD]  Us[d][c] = U[cbase+c][d]
    float* xs    = Us + US_SIZE;            // [LT][XS_LD]   xs[l][d]
    float* xt    = xs + XS_SIZE;            // [DIM][XT_LD]  xt[d][l]
    float* Ps    = xt + XT_SIZE;            // [LT][PS_LD]   Ps[l][c] = exp(att)
    float* denom = Ps + PS_SIZE;            // [CT]

    const int b     = blockIdx.y;
    const int cbase = blockIdx.x * CT;
    const int t     = threadIdx.x;

    // Micro-tile mapping: cg contiguous within a warp (smem-friendly along c).
    const int cg = t & 15;       // 0..15
    const int rg = t >> 4;       // 0..15
    const int c0 = cg * 8;       // 8 classes per thread (both GEMMs)
    const int l0 = rg * 4;       // 4 seq rows per thread (GEMM1)
    const int d0 = rg * 8;       // 8 dims per thread     (GEMM2)

    // Loader-thread fixed coordinates: thread t owns column group d4 = t&31
    // (dims 4*d4..4*d4+3) of rows l = 8k + (t>>5), k = 0..7.
    const int ld_d4 = t & 31;
    const int ld_l0 = t >> 5;

    if (t < CT) denom[t] = 0.f;

    // Load U tile transposed into smem; zero-pad invalid classes.
    for (int i = t; i < CT * DIM; i += NTHREADS) {
        int c = i >> 7;
        int d = i & 127;
        int gc = cbase + c;
        float v = (gc < NCLS) ? U[gc * DIM + d] : 0.f;
        Us[d * US_LD + c] = v;
    }

    // O accumulators: 8 classes x 4 d-pairs (pairs along d).
    u64 O2[8][4];
    #pragma unroll
    for (int j = 0; j < 8; ++j)
        #pragma unroll
        for (int k = 0; k < 4; ++k) O2[j][k] = 0ull;

    const float4* xb4 = (const float4*)(x + (size_t)b * SEQ * DIM);

    // Prefetch chunk 0 into registers (8 float4 per thread).
    float4 pf[8];
    #pragma unroll
    for (int k = 0; k < 8; ++k) {
        int gl = ld_l0 + 8 * k;               // lc = 0
        pf[k] = (gl < SEQ) ? xb4[gl * 32 + ld_d4]
                           : make_float4(0.f, 0.f, 0.f, 0.f);
    }

    for (int lc = 0; lc < SEQ; lc += LT) {
        __syncthreads();   // (A) prev GEMM2 done with xs/Ps; Us/denom ready on iter 0

        // ---- store prefetched chunk: xs (coalesced) + xt (register transpose) ----
        {
            float4* xs4 = (float4*)xs;
            #pragma unroll
            for (int k = 0; k < 8; ++k) {
                int l = ld_l0 + 8 * k;
                xs4[l * 32 + ld_d4] = pf[k];
                float* col = xt + (4 * ld_d4) * XT_LD + l;   // xt[4*d4+j][l]
                col[0 * XT_LD] = pf[k].x;
                col[1 * XT_LD] = pf[k].y;
                col[2 * XT_LD] = pf[k].z;
                col[3 * XT_LD] = pf[k].w;
            }
        }
        __syncthreads();   // (B) xs/xt ready

        // ---- GEMM1: S[l0..l0+3][c0..c0+7] = sum_d x[l][d]*U[c][d] ----
        u64 S2[4][4];
        #pragma unroll
        for (int i = 0; i < 4; ++i)
            #pragma unroll
            for (int jj = 0; jj < 4; ++jj) S2[i][jj] = 0ull;

        {
            const float* up = Us + c0;
            const float* xp = xt + l0;
            #pragma unroll 4
            for (int d = 0; d < DIM; ++d) {
                ulonglong2 a01 = *(const ulonglong2*)(up);       // c-pairs (natural)
                ulonglong2 a23 = *(const ulonglong2*)(up + 4);
                float4 xv = *(const float4*)(xp);                // 4 l-values
                up += US_LD; xp += XT_LD;
                u64 ap[4] = {a01.x, a01.y, a23.x, a23.y};
                u64 lv2[4] = {splat2(xv.x), splat2(xv.y), splat2(xv.z), splat2(xv.w)};
                #pragma unroll
                for (int i = 0; i < 4; ++i)
                    #pragma unroll
                    for (int jj = 0; jj < 4; ++jj)
                        S2[i][jj] = fma2(lv2[i], ap[jj], S2[i][jj]);
            }
        }

        // ---- P = exp(S) (zero for padded l), write Ps, accumulate denom ----
        {
            float psum[8];
            #pragma unroll
            for (int j = 0; j < 8; ++j) psum[j] = 0.f;
            #pragma unroll
            for (int i = 0; i < 4; ++i) {
                bool valid = (lc + l0 + i) < SEQ;
                float s[8];
                #pragma unroll
                for (int jj = 0; jj < 4; ++jj)
                    unpack2(S2[i][jj], s[2 * jj], s[2 * jj + 1]);
                float p[8];
                #pragma unroll
                for (int j = 0; j < 8; ++j) {
                    p[j] = valid ? __expf(s[j]) : 0.f;
                    psum[j] += p[j];
                }
                float4* row = (float4*)(Ps + (l0 + i) * PS_LD + c0);
                row[0] = make_float4(p[0], p[1], p[2], p[3]);
                row[1] = make_float4(p[4], p[5], p[6], p[7]);
            }
            #pragma unroll
            for (int j = 0; j < 8; ++j)
                atomicAdd(&denom[c0 + j], psum[j]);
        }
        __syncthreads();   // (D) Ps ready

        // ---- prefetch next chunk (LDG latency hides under GEMM2) ----
        {
            int lc_next = lc + LT;
            if (lc_next < SEQ) {
                #pragma unroll
                for (int k = 0; k < 8; ++k) {
                    int gl = lc_next + ld_l0 + 8 * k;
                    pf[k] = (gl < SEQ) ? xb4[gl * 32 + ld_d4]
                                       : make_float4(0.f, 0.f, 0.f, 0.f);
                }
            }
        }

        // ---- GEMM2: O[c0..c0+7][d0..d0+7] += P[c][l]*x[l][d] (pairs along d) ----
        {
            const float* pp = Ps + c0;
            const float* bp = xs + d0;
            #pragma unroll 2
            for (int l = 0; l < LT; ++l) {
                float4 p0 = *(const float4*)(pp);                // 8 P values
                float4 p1 = *(const float4*)(pp + 4);
                ulonglong2 b01 = *(const ulonglong2*)(bp);       // d-pairs (natural)
                ulonglong2 b23 = *(const ulonglong2*)(bp + 4);
                pp += PS_LD; bp += XS_LD;
                u64 bv[4] = {b01.x, b01.y, b23.x, b23.y};
                u64 pv2[8] = {splat2(p0.x), splat2(p0.y), splat2(p0.z), splat2(p0.w),
                              splat2(p1.x), splat2(p1.y), splat2(p1.z), splat2(p1.w)};
                #pragma unroll
                for (int j = 0; j < 8; ++j)
                    #pragma unroll
                    for (int kk = 0; kk < 4; ++kk)
                        O2[j][kk] = fma2(pv2[j], bv[kk], O2[j][kk]);
            }
        }
    }

    __syncthreads();   // denom final

    // ---- epilogue: m = O / denom ----
    #pragma unroll
    for (int j = 0; j < 8; ++j) {
        int gc = cbase + c0 + j;
        if (gc >= NCLS) continue;
        float inv = 1.f / denom[c0 + j];
        float o[8];
        #pragma unroll
        for (int kk = 0; kk < 4; ++kk)
            unpack2(O2[j][kk], o[2 * kk], o[2 * kk + 1]);
        float* op = out + ((size_t)b * NCLS + gc) * DIM + d0;
        *(float4*)(op)     = make_float4(o[0]*inv, o[1]*inv, o[2]*inv, o[3]*inv);
        *(float4*)(op + 4) = make_float4(o[4]*inv, o[5]*inv, o[6]*inv, o[7]*inv);
    }
}

extern "C" void kernel_launch(void* const* d_in, const int* in_sizes, int n_in,
                              void* d_out, int out_size)
{
    const float* x = (const float*)d_in[0];
    const float* U = (const float*)d_in[1];
    // Defensive: tolerate swapped metadata order.
    if (n_in >= 2 && in_sizes[0] == NCLS * DIM && in_sizes[1] == BATCH * SEQ * DIM) {
        const float* tmp = x; x = U; U = tmp;
    }
    float* out = (float*)d_out;

    size_t smem = SMEM_FLOATS * sizeof(float);   // 168448 B
    cudaFuncSetAttribute(lwa_kernel, cudaFuncAttributeMaxDynamicSharedMemorySize, (int)smem);

    dim3 grid((NCLS + CT - 1) / CT, BATCH);      // 70 x 8 = 560 CTAs
    lwa_kernel<<<grid, NTHREADS, smem>>>(x, U, out);
}

// round 9
// speedup vs baseline: 3.0430x; 3.0430x over previous
#include <cuda_runtime.h>
#include <cuda_bf16.h>
#include <cstdint>

// LabelWiseAttn fused flash kernel — mma.sync (HMMA bf16, fp32 accum),
// 2-term bf16 split for fp32-class accuracy. Baseline sm_103 target
// (no tcgen05 — harness compiles PTX for sm_103, not sm_103a).
//   att = U x^T, alpha = softmax_l(att), m = alpha x   (|att| <~ 1.1)
// Per CTA: (batch, 128 classes); L streamed in 64-chunks.
// GEMM1: S[128c x 64l] = Uh*xh + Uh*xl + Ul*xh   (A=U ldmatrix, B=x ldmatrix)
// GEMM2: O[128c x 128d] += Ph*xh + Ph*xl + Pl*xh (A=P ldmatrix, B=x ldmatrix.trans)

#define BATCH    8
#define SEQ      2500
#define DIM      128
#define NCLS     8921
#define CT       128
#define LT       64
#define NCHUNK   40
#define NTHREADS 256

// smem byte map
#define SM_DEN   0
#define SM_UHI   1024
#define U_STR    272                   // 128 bf16 + 8 pad (16 mod 128 -> ldmatrix conflict-free)
#define U_SZ     (128 * U_STR)         // 34816
#define SM_ULO   (SM_UHI + U_SZ)
#define SM_XHI   (SM_ULO + U_SZ)
#define X_STR    272
#define X_SZ     (64 * X_STR)          // 17408
#define SM_XLO   (SM_XHI + X_SZ)
#define SM_PHI   (SM_XLO + X_SZ)
#define P_STR    144                   // 64 bf16 + 8 pad
#define P_SZ     (128 * P_STR)         // 18432
#define SM_PLO   (SM_PHI + P_SZ)
#define SM_TOTAL (SM_PLO + P_SZ)       // 142336 B

__device__ __forceinline__ uint32_t smem_u32(const void* p) {
    uint32_t a;
    asm("{ .reg .u64 t; cvta.to.shared.u64 t, %1; cvt.u32.u64 %0, t; }" : "=r"(a) : "l"(p));
    return a;
}
__device__ __forceinline__ void ldsm4(uint32_t* r, uint32_t a) {
    asm volatile("ldmatrix.sync.aligned.m8n8.x4.shared.b16 {%0,%1,%2,%3}, [%4];"
                 : "=r"(r[0]), "=r"(r[1]), "=r"(r[2]), "=r"(r[3]) : "r"(a));
}
__device__ __forceinline__ void ldsm4t(uint32_t* r, uint32_t a) {
    asm volatile("ldmatrix.sync.aligned.m8n8.x4.trans.shared.b16 {%0,%1,%2,%3}, [%4];"
                 : "=r"(r[0]), "=r"(r[1]), "=r"(r[2]), "=r"(r[3]) : "r"(a));
}
__device__ __forceinline__ void mma16816(float* d, const uint32_t* a, uint32_t b0, uint32_t b1) {
    asm volatile("mma.sync.aligned.m16n8k16.row.col.f32.bf16.bf16.f32 "
                 "{%0,%1,%2,%3}, {%4,%5,%6,%7}, {%8,%9}, {%0,%1,%2,%3};"
                 : "+f"(d[0]), "+f"(d[1]), "+f"(d[2]), "+f"(d[3])
                 : "r"(a[0]), "r"(a[1]), "r"(a[2]), "r"(a[3]), "r"(b0), "r"(b1));
}
__device__ __forceinline__ uint32_t pack2(__nv_bfloat16 a, __nv_bfloat16 b) {
    return ((uint32_t)__bfloat16_as_ushort(b) << 16) | (uint32_t)__bfloat16_as_ushort(a);
}
// split 4 floats -> 4 bf16 hi (8B) + 4 bf16 lo (8B)
__device__ __forceinline__ void split_store8(char* hb, char* lb, float4 v) {
    __nv_bfloat16 h0 = __float2bfloat16(v.x), h1 = __float2bfloat16(v.y);
    __nv_bfloat16 h2 = __float2bfloat16(v.z), h3 = __float2bfloat16(v.w);
    *(uint2*)hb = make_uint2(pack2(h0, h1), pack2(h2, h3));
    *(uint2*)lb = make_uint2(
        pack2(__float2bfloat16(v.x - __bfloat162float(h0)),
              __float2bfloat16(v.y - __bfloat162float(h1))),
        pack2(__float2bfloat16(v.z - __bfloat162float(h2)),
              __float2bfloat16(v.w - __bfloat162float(h3))));
}

__global__ __launch_bounds__(NTHREADS, 1)
void lwa_mma(const float* __restrict__ x, const float* __restrict__ U,
             float* __restrict__ out)
{
    extern __shared__ char smem[];
    const uint32_t sb = smem_u32(smem);
    const int t = threadIdx.x, lane = t & 31, warp = t >> 5;
    const int b = blockIdx.y, cbase = blockIdx.x * CT;

    const int wc = (warp & 3) * 32;    // class tile base (both GEMMs)
    const int wl = (warp >> 2) * 32;   // l tile base (GEMM1)
    const int wd = (warp >> 2) * 64;   // d tile base (GEMM2)

    // ldmatrix lane patterns
    const int arow  = (lane & 7) + 8 * ((lane >> 3) & 1);  // A-type + B-trans rows
    const int ahalf = lane >> 4;
    const int brow  = (lane & 7) + 8 * (lane >> 4);        // B non-trans rows
    const int bhalf = (lane >> 3) & 1;

    float* denom = (float*)(smem + SM_DEN);
    if (t < CT) denom[t] = 0.f;

    // ---- U prologue: split into Uhi/Ulo [128c x 128d] bf16 ----
    {
        const float4* U4 = (const float4*)U;
        int d4 = t & 31, c0 = t >> 5;
        #pragma unroll
        for (int k = 0; k < 16; ++k) {
            int c = c0 + 8 * k, gc = cbase + c;
            float4 v = (gc < NCLS) ? U4[(size_t)gc * 32 + d4]
                                   : make_float4(0.f, 0.f, 0.f, 0.f);
            split_store8(smem + SM_UHI + c * U_STR + d4 * 8,
                         smem + SM_ULO + c * U_STR + d4 * 8, v);
        }
    }

    float O[2][8][4];
    #pragma unroll
    for (int i = 0; i < 2; ++i)
        #pragma unroll
        for (int j = 0; j < 8; ++j)
            #pragma unroll
            for (int k = 0; k < 4; ++k) O[i][j][k] = 0.f;

    const float4* xb4 = (const float4*)(x + (size_t)b * SEQ * DIM);

    for (int ch = 0; ch < NCHUNK; ++ch) {
        const int lc = ch * LT;
        __syncthreads();   // prev GEMM2 done reading x/P; U+denom ready on ch=0

        // ---- load x chunk, split into xhi/xlo [64l x 128d] ----
        {
            int d4 = t & 31, l0 = t >> 5;
            #pragma unroll
            for (int k = 0; k < 8; ++k) {
                int l = l0 + 8 * k, gl = lc + l;
                float4 v = (gl < SEQ) ? xb4[(size_t)gl * 32 + d4]
                                      : make_float4(0.f, 0.f, 0.f, 0.f);
                split_store8(smem + SM_XHI + l * X_STR + d4 * 8,
                             smem + SM_XLO + l * X_STR + d4 * 8, v);
            }
        }
        __syncthreads();   // x ready

        // ---- GEMM1: S[32c x 32l] per warp, 3 split passes ----
        float S[2][4][4];
        #pragma unroll
        for (int i = 0; i < 2; ++i)
            #pragma unroll
            for (int j = 0; j < 4; ++j)
                #pragma unroll
                for (int k = 0; k < 4; ++k) S[i][j][k] = 0.f;

        #pragma unroll
        for (int ks = 0; ks < 8; ++ks) {
            uint32_t uh[2][4], ul[2][4], bh[2][4], bl[2][4];
            #pragma unroll
            for (int mt = 0; mt < 2; ++mt) {
                uint32_t off = (uint32_t)((wc + 16 * mt + arow) * U_STR + ks * 32 + ahalf * 16);
                ldsm4(uh[mt], sb + SM_UHI + off);
                ldsm4(ul[mt], sb + SM_ULO + off);
            }
            #pragma unroll
            for (int g = 0; g < 2; ++g) {
                uint32_t off = (uint32_t)((wl + 16 * g + brow) * X_STR + ks * 32 + bhalf * 16);
                ldsm4(bh[g], sb + SM_XHI + off);
                ldsm4(bl[g], sb + SM_XLO + off);
            }
            #pragma unroll
            for (int mt = 0; mt < 2; ++mt)
                #pragma unroll
                for (int g = 0; g < 2; ++g) {
                    mma16816(S[mt][2*g  ], uh[mt], bh[g][0], bh[g][1]);
                    mma16816(S[mt][2*g+1], uh[mt], bh[g][2], bh[g][3]);
                    mma16816(S[mt][2*g  ], uh[mt], bl[g][0], bl[g][1]);
                    mma16816(S[mt][2*g+1], uh[mt], bl[g][2], bl[g][3]);
                    mma16816(S[mt][2*g  ], ul[mt], bh[g][0], bh[g][1]);
                    mma16816(S[mt][2*g+1], ul[mt], bh[g][2], bh[g][3]);
                }
        }

        // ---- softmax: exp + tail-mask, denom atomics, split-store P ----
        #pragma unroll
        for (int mt = 0; mt < 2; ++mt) {
            int r0 = wc + 16 * mt + (lane >> 2);
            float rs0 = 0.f, rs1 = 0.f;
            #pragma unroll
            for (int nt = 0; nt < 4; ++nt) {
                int lcol = wl + 8 * nt + 2 * (lane & 3);
                int gl = lc + lcol;
                bool v0 = gl < SEQ, v1 = (gl + 1) < SEQ;
                float p00 = v0 ? __expf(S[mt][nt][0]) : 0.f;
                float p01 = v1 ? __expf(S[mt][nt][1]) : 0.f;
                float p10 = v0 ? __expf(S[mt][nt][2]) : 0.f;
                float p11 = v1 ? __expf(S[mt][nt][3]) : 0.f;
                rs0 += p00 + p01; rs1 += p10 + p11;
                __nv_bfloat16 h00 = __float2bfloat16(p00), h01 = __float2bfloat16(p01);
                __nv_bfloat16 h10 = __float2bfloat16(p10), h11 = __float2bfloat16(p11);
                *(uint32_t*)(smem + SM_PHI + r0 * P_STR + lcol * 2) = pack2(h00, h01);
                *(uint32_t*)(smem + SM_PHI + (r0 + 8) * P_STR + lcol * 2) = pack2(h10, h11);
                *(uint32_t*)(smem + SM_PLO + r0 * P_STR + lcol * 2) =
                    pack2(__float2bfloat16(p00 - __bfloat162float(h00)),
                          __float2bfloat16(p01 - __bfloat162float(h01)));
                *(uint32_t*)(smem + SM_PLO + (r0 + 8) * P_STR + lcol * 2) =
                    pack2(__float2bfloat16(p10 - __bfloat162float(h10)),
                          __float2bfloat16(p11 - __bfloat162float(h11)));
            }
            atomicAdd(&denom[r0], rs0);
            atomicAdd(&denom[r0 + 8], rs1);
        }
        __syncthreads();   // P ready

        // ---- GEMM2: O[32c x 64d] per warp += P * x, 3 split passes ----
        #pragma unroll
        for (int ks = 0; ks < 4; ++ks) {
            uint32_t ph[2][4], pl[2][4];
            #pragma unroll
            for (int mt = 0; mt < 2; ++mt) {
                uint32_t off = (uint32_t)((wc + 16 * mt + arow) * P_STR + ks * 32 + ahalf * 16);
                ldsm4(ph[mt], sb + SM_PHI + off);
                ldsm4(pl[mt], sb + SM_PLO + off);
            }
            #pragma unroll
            for (int g = 0; g < 4; ++g) {
                uint32_t xh[4], xl[4];
                uint32_t off = (uint32_t)((16 * ks + arow) * X_STR + (wd + 16 * g) * 2 + ahalf * 16);
                ldsm4t(xh, sb + SM_XHI + off);
                ldsm4t(xl, sb + SM_XLO + off);
                #pragma unroll
                for (int mt = 0; mt < 2; ++mt) {
                    mma16816(O[mt][2*g  ], ph[mt], xh[0], xh[1]);
                    mma16816(O[mt][2*g+1], ph[mt], xh[2], xh[3]);
                    mma16816(O[mt][2*g  ], ph[mt], xl[0], xl[1]);
                    mma16816(O[mt][2*g+1], ph[mt], xl[2], xl[3]);
                    mma16816(O[mt][2*g  ], pl[mt], xh[0], xh[1]);
                    mma16816(O[mt][2*g+1], pl[mt], xh[2], xh[3]);
                }
            }
        }
    }

    // ---- epilogue: m = O / denom ----
    #pragma unroll
    for (int mt = 0; mt < 2; ++mt) {
        int r = wc + 16 * mt + (lane >> 2);
        int gc0 = cbase + r, gc1 = gc0 + 8;
        float i0 = 1.f / denom[r], i1 = 1.f / denom[r + 8];
        #pragma unroll
        for (int ng = 0; ng < 8; ++ng) {
            int d = wd + 8 * ng + 2 * (lane & 3);
            if (gc0 < NCLS)
                *(float2*)(out + ((size_t)b * NCLS + gc0) * DIM + d) =
                    make_float2(O[mt][ng][0] * i0, O[mt][ng][1] * i0);
            if (gc1 < NCLS)
                *(float2*)(out + ((size_t)b * NCLS + gc1) * DIM + d) =
                    make_float2(O[mt][ng][2] * i1, O[mt][ng][3] * i1);
        }
    }
}

extern "C" void kernel_launch(void* const* d_in, const int* in_sizes, int n_in,
                              void* d_out, int out_size)
{
    const float* x = (const float*)d_in[0];
    const float* U = (const float*)d_in[1];
    if (n_in >= 2 && in_sizes[0] == NCLS * DIM && in_sizes[1] == BATCH * SEQ * DIM) {
        const float* tmp = x; x = U; U = tmp;
    }
    float* out = (float*)d_out;

    cudaFuncSetAttribute(lwa_mma, cudaFuncAttributeMaxDynamicSharedMemorySize, SM_TOTAL);
    dim3 grid((NCLS + CT - 1) / CT, BATCH);   // 70 x 8 = 560 CTAs
    lwa_mma<<<grid, NTHREADS, SM_TOTAL>>>(x, U, out);
}